// round 3
// baseline (speedup 1.0000x reference)
#include <cuda_runtime.h>
#include <cuda_bf16.h>
#include <math.h>

#define B_ 8
#define T_ 8192
#define WD_ 128
#define SD_ 512
#define FINAL_ 6145
#define XSTRIDE ((size_t)T_ * WD_)

// Scratch (static device globals; runtime allocation is forbidden)
__device__ float g_x0[(size_t)B_ * T_ * WD_];          // 32 MB
__device__ float g_x1[(size_t)B_ * T_ * WD_];          // 32 MB
__device__ float g_skip[(size_t)B_ * FINAL_ * SD_];    // ~101 MB

__device__ __forceinline__ float sigm(float x) {
    return 1.0f / (1.0f + __expf(-x));
}

// ---------------------------------------------------------------------------
// Embedding: x[b][t][c] = emb[y[b][t]][c], layout [B][T][128] (channel-contig)
// ---------------------------------------------------------------------------
__global__ void embed_kernel(const int* __restrict__ y,
                             const float* __restrict__ emb,
                             float* __restrict__ x) {
    size_t i = (size_t)blockIdx.x * blockDim.x + threadIdx.x;  // float4 index
    size_t bt = i >> 5;
    int c4 = (int)(i & 31);
    int idx = y[bt];
    ((float4*)x)[i] = ((const float4*)(emb + (size_t)idx * WD_))[c4];
}

// ---------------------------------------------------------------------------
// Fused WaveNet layer:
//   in_act = x[t]*Wd0 + x[t+d]*Wd1 + bd            (M=64, N=256, K=128 x2)
//   acts   = tanh(in_act[:128]) * sigmoid(in_act[128:])
//   xout[t]= acts*Wr + br + x[t+d]                 (N=128)
//   skip[s]+= acts*Ws + bs   (s = t - (Tout-6145)) (N=512, two 256 chunks)
// Block: 256 threads, 64 time rows. Microtile: 8 rows x 8 cols per thread.
// tn = tid&31 (col group), tm = tid>>5 (row group; warp-uniform => A broadcast)
// ---------------------------------------------------------------------------
#define SMEM_FLOATS (3 * 64 * 128 + 16 * 256)

__global__ __launch_bounds__(256)
void layer_kernel(const float* __restrict__ xin, float* __restrict__ xout,
                  float* __restrict__ skip,
                  const float* __restrict__ Wd,   // [2][128][256]
                  const float* __restrict__ bd,   // [256]
                  const float* __restrict__ Wr,   // [128][128]
                  const float* __restrict__ br,   // [128]
                  const float* __restrict__ Ws,   // [128][512]
                  const float* __restrict__ bs,   // [512]
                  int Lin, int d, int first)
{
    extern __shared__ float sm[];
    float* As0  = sm;                 // [64][128] x[t0+r]
    float* As1  = sm + 64 * 128;      // [64][128] x[t0+r+d]
    float* Acts = sm + 2 * 64 * 128;  // [64][128]
    float* Bs   = sm + 3 * 64 * 128;  // [16][256] weight slice

    const int Tout = Lin - d;
    const int b   = blockIdx.y;
    const int t0  = blockIdx.x * 64;
    const int tid = threadIdx.x;
    const int tn  = tid & 31;
    const int tm  = tid >> 5;

    const float* xb = xin + (size_t)b * XSTRIDE;

    // Load both A tiles (clamped rows for the ragged tail)
    #pragma unroll
    for (int u = 0; u < 8; u++) {
        int idx = u * 256 + tid;       // float4 index into [64][32]
        int r = idx >> 5, c4 = idx & 31;
        int t = t0 + r; if (t > Tout - 1) t = Tout - 1;
        ((float4*)As0)[idx] = ((const float4*)(xb + (size_t)t * WD_))[c4];
        ((float4*)As1)[idx] = ((const float4*)(xb + (size_t)(t + d) * WD_))[c4];
    }

    float acc[64];
    #pragma unroll
    for (int i = 0; i < 64; i++) acc[i] = 0.0f;

    // ---- Phase 1: conv GEMM (two taps) ----
    #pragma unroll 1
    for (int h = 0; h < 2; h++) {
        const float* W = Wd + h * (128 * 256);
        const float* A = (h ? As1 : As0) + tm * 8 * 128;
        #pragma unroll 1
        for (int ks = 0; ks < 8; ks++) {
            __syncthreads();
            #pragma unroll
            for (int u = 0; u < 4; u++) {
                int idx = u * 256 + tid;   // 1024 float4 = [16][256]
                ((float4*)Bs)[idx] = ((const float4*)(W + ks * 16 * 256))[idx];
            }
            __syncthreads();
            #pragma unroll
            for (int k = 0; k < 16; k++) {
                float a[8];
                #pragma unroll
                for (int i = 0; i < 8; i++) a[i] = A[i * 128 + ks * 16 + k];
                float4 b0 = ((const float4*)(Bs + k * 256))[tn];
                float4 b1 = ((const float4*)(Bs + k * 256 + 128))[tn];
                #pragma unroll
                for (int i = 0; i < 8; i++) {
                    acc[i*8+0] = fmaf(a[i], b0.x, acc[i*8+0]);
                    acc[i*8+1] = fmaf(a[i], b0.y, acc[i*8+1]);
                    acc[i*8+2] = fmaf(a[i], b0.z, acc[i*8+2]);
                    acc[i*8+3] = fmaf(a[i], b0.w, acc[i*8+3]);
                    acc[i*8+4] = fmaf(a[i], b1.x, acc[i*8+4]);
                    acc[i*8+5] = fmaf(a[i], b1.y, acc[i*8+5]);
                    acc[i*8+6] = fmaf(a[i], b1.z, acc[i*8+6]);
                    acc[i*8+7] = fmaf(a[i], b1.w, acc[i*8+7]);
                }
            }
        }
    }

    // ---- Gate: acts[c] = tanh(in[c]+bd[c]) * sigmoid(in[c+128]+bd[c+128]) ----
    {
        float4 bd0 = ((const float4*)bd)[tn];
        float4 bd1 = ((const float4*)(bd + 128))[tn];
        #pragma unroll
        for (int i = 0; i < 8; i++) {
            float4 v;
            v.x = tanhf(acc[i*8+0] + bd0.x) * sigm(acc[i*8+4] + bd1.x);
            v.y = tanhf(acc[i*8+1] + bd0.y) * sigm(acc[i*8+5] + bd1.y);
            v.z = tanhf(acc[i*8+2] + bd0.z) * sigm(acc[i*8+6] + bd1.z);
            v.w = tanhf(acc[i*8+3] + bd0.w) * sigm(acc[i*8+7] + bd1.w);
            ((float4*)(Acts + (tm * 8 + i) * 128))[tn] = v;
        }
    }

    const float* ActsA = Acts + tm * 8 * 128;

    // ---- Phase 2: residual GEMM (N=128) ----
    {
        float racc[32];
        #pragma unroll
        for (int i = 0; i < 32; i++) racc[i] = 0.0f;
        #pragma unroll 1
        for (int ks = 0; ks < 8; ks++) {
            __syncthreads();
            #pragma unroll
            for (int u = 0; u < 2; u++) {
                int idx = u * 256 + tid;   // 512 float4 = [16][128]
                ((float4*)Bs)[idx] = ((const float4*)(Wr + ks * 16 * 128))[idx];
            }
            __syncthreads();
            #pragma unroll
            for (int k = 0; k < 16; k++) {
                float a[8];
                #pragma unroll
                for (int i = 0; i < 8; i++) a[i] = ActsA[i * 128 + ks * 16 + k];
                float4 bv = ((const float4*)(Bs + k * 128))[tn];
                #pragma unroll
                for (int i = 0; i < 8; i++) {
                    racc[i*4+0] = fmaf(a[i], bv.x, racc[i*4+0]);
                    racc[i*4+1] = fmaf(a[i], bv.y, racc[i*4+1]);
                    racc[i*4+2] = fmaf(a[i], bv.z, racc[i*4+2]);
                    racc[i*4+3] = fmaf(a[i], bv.w, racc[i*4+3]);
                }
            }
        }
        float4 brv = ((const float4*)br)[tn];
        #pragma unroll
        for (int i = 0; i < 8; i++) {
            int t = t0 + tm * 8 + i;
            if (t < Tout) {
                float4 xv = ((const float4*)(As1 + (tm * 8 + i) * 128))[tn];
                float4 o;
                o.x = racc[i*4+0] + brv.x + xv.x;
                o.y = racc[i*4+1] + brv.y + xv.y;
                o.z = racc[i*4+2] + brv.z + xv.z;
                o.w = racc[i*4+3] + brv.w + xv.w;
                ((float4*)(xout + (size_t)b * XSTRIDE + (size_t)t * WD_))[tn] = o;
            }
        }
    }

    // ---- Phase 3: skip GEMM (N=512, two 256-col chunks) ----
    const int s0 = Tout - FINAL_;
    #pragma unroll 1
    for (int q = 0; q < 2; q++) {
        #pragma unroll
        for (int i = 0; i < 64; i++) acc[i] = 0.0f;
        #pragma unroll 1
        for (int ks = 0; ks < 8; ks++) {
            __syncthreads();
            #pragma unroll
            for (int u = 0; u < 4; u++) {
                int idx = u * 256 + tid;   // [16][256]
                int row = idx >> 6, c4 = idx & 63;
                ((float4*)Bs)[idx] =
                    ((const float4*)(Ws + (size_t)(ks * 16 + row) * 512 + q * 256))[c4];
            }
            __syncthreads();
            #pragma unroll
            for (int k = 0; k < 16; k++) {
                float a[8];
                #pragma unroll
                for (int i = 0; i < 8; i++) a[i] = ActsA[i * 128 + ks * 16 + k];
                float4 b0 = ((const float4*)(Bs + k * 256))[tn];
                float4 b1 = ((const float4*)(Bs + k * 256 + 128))[tn];
                #pragma unroll
                for (int i = 0; i < 8; i++) {
                    acc[i*8+0] = fmaf(a[i], b0.x, acc[i*8+0]);
                    acc[i*8+1] = fmaf(a[i], b0.y, acc[i*8+1]);
                    acc[i*8+2] = fmaf(a[i], b0.z, acc[i*8+2]);
                    acc[i*8+3] = fmaf(a[i], b0.w, acc[i*8+3]);
                    acc[i*8+4] = fmaf(a[i], b1.x, acc[i*8+4]);
                    acc[i*8+5] = fmaf(a[i], b1.y, acc[i*8+5]);
                    acc[i*8+6] = fmaf(a[i], b1.z, acc[i*8+6]);
                    acc[i*8+7] = fmaf(a[i], b1.w, acc[i*8+7]);
                }
            }
        }
        float4 bs0 = ((const float4*)(bs + q * 256))[tn];
        float4 bs1 = ((const float4*)(bs + q * 256 + 128))[tn];
        #pragma unroll
        for (int i = 0; i < 8; i++) {
            int t = t0 + tm * 8 + i;
            if (t < Tout && t >= s0) {
                float* p = skip + ((size_t)b * FINAL_ + (t - s0)) * SD_ + q * 256;
                float4 v0, v1;
                v0.x = acc[i*8+0] + bs0.x; v0.y = acc[i*8+1] + bs0.y;
                v0.z = acc[i*8+2] + bs0.z; v0.w = acc[i*8+3] + bs0.w;
                v1.x = acc[i*8+4] + bs1.x; v1.y = acc[i*8+5] + bs1.y;
                v1.z = acc[i*8+6] + bs1.z; v1.w = acc[i*8+7] + bs1.w;
                if (!first) {
                    float4 o0 = ((const float4*)p)[tn];
                    float4 o1 = ((const float4*)(p + 128))[tn];
                    v0.x += o0.x; v0.y += o0.y; v0.z += o0.z; v0.w += o0.w;
                    v1.x += o1.x; v1.y += o1.y; v1.z += o1.z; v1.w += o1.w;
                }
                ((float4*)p)[tn] = v0;
                ((float4*)(p + 128))[tn] = v1;
            }
        }
    }
}

// ---------------------------------------------------------------------------
// Fused post stage:
//   hid = relu(relu(skip) @ W1)   (K=512, N=512) -> staged in smem
//   out[b][o][t] = (hid @ W2)[t][o]  (K=512, N=256, transposed store)
// Block: 64 time rows, 256 threads. Hid tile [64][512] lives in smem.
// ---------------------------------------------------------------------------
#define PF_SMEM_FLOATS (64 * 512 + 16 * 256 + 64 * 16)

__global__ __launch_bounds__(256)
void post_fused_kernel(const float* __restrict__ skip,
                       const float* __restrict__ W1,
                       const float* __restrict__ W2,
                       float* __restrict__ out)
{
    extern __shared__ float sm2[];
    float* Hid = sm2;                    // [64][512]
    float* Bs  = sm2 + 64 * 512;         // [16][256]
    float* As  = sm2 + 64 * 512 + 16 * 256;  // [64][16]

    const int b  = blockIdx.y;
    const int t0 = blockIdx.x * 64;
    const int tid = threadIdx.x, tn = tid & 31, tm = tid >> 5;

    // ---- Phase A: Hid = relu(relu(skip) @ W1), two 256-col chunks ----
    #pragma unroll 1
    for (int q = 0; q < 2; q++) {
        float acc[64];
        #pragma unroll
        for (int i = 0; i < 64; i++) acc[i] = 0.0f;

        #pragma unroll 1
        for (int ks = 0; ks < 32; ks++) {
            __syncthreads();
            {
                int r = tid >> 2, c4 = tid & 3;
                int t = t0 + r; if (t > FINAL_ - 1) t = FINAL_ - 1;
                float4 v = ((const float4*)(skip + ((size_t)b * FINAL_ + t) * SD_ + ks * 16))[c4];
                v.x = fmaxf(v.x, 0.0f); v.y = fmaxf(v.y, 0.0f);
                v.z = fmaxf(v.z, 0.0f); v.w = fmaxf(v.w, 0.0f);
                ((float4*)As)[tid] = v;
            }
            #pragma unroll
            for (int u = 0; u < 4; u++) {
                int idx = u * 256 + tid;
                int row = idx >> 6, c4 = idx & 63;
                ((float4*)Bs)[idx] =
                    ((const float4*)(W1 + (size_t)(ks * 16 + row) * 512 + q * 256))[c4];
            }
            __syncthreads();
            #pragma unroll
            for (int k = 0; k < 16; k++) {
                float a[8];
                #pragma unroll
                for (int i = 0; i < 8; i++) a[i] = As[(tm * 8 + i) * 16 + k];
                float4 b0 = ((const float4*)(Bs + k * 256))[tn];
                float4 b1 = ((const float4*)(Bs + k * 256 + 128))[tn];
                #pragma unroll
                for (int i = 0; i < 8; i++) {
                    acc[i*8+0] = fmaf(a[i], b0.x, acc[i*8+0]);
                    acc[i*8+1] = fmaf(a[i], b0.y, acc[i*8+1]);
                    acc[i*8+2] = fmaf(a[i], b0.z, acc[i*8+2]);
                    acc[i*8+3] = fmaf(a[i], b0.w, acc[i*8+3]);
                    acc[i*8+4] = fmaf(a[i], b1.x, acc[i*8+4]);
                    acc[i*8+5] = fmaf(a[i], b1.y, acc[i*8+5]);
                    acc[i*8+6] = fmaf(a[i], b1.z, acc[i*8+6]);
                    acc[i*8+7] = fmaf(a[i], b1.w, acc[i*8+7]);
                }
            }
        }
        // Store relu(acc) into the Hid smem tile (thread-private region)
        #pragma unroll
        for (int i = 0; i < 8; i++) {
            float* p = Hid + (tm * 8 + i) * 512 + q * 256;
            float4 v0, v1;
            v0.x = fmaxf(acc[i*8+0], 0.0f); v0.y = fmaxf(acc[i*8+1], 0.0f);
            v0.z = fmaxf(acc[i*8+2], 0.0f); v0.w = fmaxf(acc[i*8+3], 0.0f);
            v1.x = fmaxf(acc[i*8+4], 0.0f); v1.y = fmaxf(acc[i*8+5], 0.0f);
            v1.z = fmaxf(acc[i*8+6], 0.0f); v1.w = fmaxf(acc[i*8+7], 0.0f);
            ((float4*)p)[tn] = v0;
            ((float4*)(p + 128))[tn] = v1;
        }
    }

    // ---- Phase B: out = Hid @ W2 (K=512, N=256), transposed store ----
    {
        float acc[64];
        #pragma unroll
        for (int i = 0; i < 64; i++) acc[i] = 0.0f;

        const float* HidA = Hid + tm * 8 * 512;
        #pragma unroll 1
        for (int ks = 0; ks < 32; ks++) {
            __syncthreads();   // first iter also orders Hid writes vs reads
            #pragma unroll
            for (int u = 0; u < 4; u++) {
                int idx = u * 256 + tid;
                int row = idx >> 6, c4 = idx & 63;
                ((float4*)Bs)[idx] =
                    ((const float4*)(W2 + (size_t)(ks * 16 + row) * 256))[c4];
            }
            __syncthreads();
            #pragma unroll
            for (int k = 0; k < 16; k++) {
                float a[8];
                #pragma unroll
                for (int i = 0; i < 8; i++) a[i] = HidA[i * 512 + ks * 16 + k];
                float4 b0 = ((const float4*)(Bs + k * 256))[tn];
                float4 b1 = ((const float4*)(Bs + k * 256 + 128))[tn];
                #pragma unroll
                for (int i = 0; i < 8; i++) {
                    acc[i*8+0] = fmaf(a[i], b0.x, acc[i*8+0]);
                    acc[i*8+1] = fmaf(a[i], b0.y, acc[i*8+1]);
                    acc[i*8+2] = fmaf(a[i], b0.z, acc[i*8+2]);
                    acc[i*8+3] = fmaf(a[i], b0.w, acc[i*8+3]);
                    acc[i*8+4] = fmaf(a[i], b1.x, acc[i*8+4]);
                    acc[i*8+5] = fmaf(a[i], b1.y, acc[i*8+5]);
                    acc[i*8+6] = fmaf(a[i], b1.z, acc[i*8+6]);
                    acc[i*8+7] = fmaf(a[i], b1.w, acc[i*8+7]);
                }
            }
        }
        #pragma unroll
        for (int i = 0; i < 8; i++) {
            int t = t0 + tm * 8 + i;
            if (t < FINAL_) {
                #pragma unroll
                for (int j = 0; j < 4; j++) {
                    out[((size_t)b * 256 + (tn * 4 + j)) * FINAL_ + t]       = acc[i*8+j];
                    out[((size_t)b * 256 + (128 + tn * 4 + j)) * FINAL_ + t] = acc[i*8+4+j];
                }
            }
        }
    }
}

// ---------------------------------------------------------------------------
extern "C" void kernel_launch(void* const* d_in, const int* in_sizes, int n_in,
                              void* d_out, int out_size)
{
    const int*   y   = (const int*)  d_in[0];
    const float* emb = (const float*)d_in[1];
    const float* Wd  = (const float*)d_in[2];
    const float* bd  = (const float*)d_in[3];
    const float* Wr  = (const float*)d_in[4];
    const float* br  = (const float*)d_in[5];
    const float* Ws  = (const float*)d_in[6];
    const float* bs  = (const float*)d_in[7];
    const float* p1  = (const float*)d_in[8];
    const float* p2  = (const float*)d_in[9];
    float* out = (float*)d_out;

    float *x0, *x1, *skip;
    cudaGetSymbolAddress((void**)&x0,   g_x0);
    cudaGetSymbolAddress((void**)&x1,   g_x1);
    cudaGetSymbolAddress((void**)&skip, g_skip);

    static const int dil[20] = {1,2,4,8,16,32,64,128,256,512,
                                1,2,4,8,16,32,64,128,256,512};

    size_t smem = SMEM_FLOATS * sizeof(float);
    cudaFuncSetAttribute(layer_kernel,
                         cudaFuncAttributeMaxDynamicSharedMemorySize, (int)smem);
    size_t pf_smem = PF_SMEM_FLOATS * sizeof(float);
    cudaFuncSetAttribute(post_fused_kernel,
                         cudaFuncAttributeMaxDynamicSharedMemorySize, (int)pf_smem);

    embed_kernel<<<(B_ * T_ * WD_ / 4) / 256, 256>>>(y, emb, x0);

    float* bufs[2] = {x0, x1};
    int Lin = T_;
    for (int i = 0; i < 20; i++) {
        int d = dil[i];
        int Tout = Lin - d;
        dim3 grid((Tout + 63) / 64, B_);
        layer_kernel<<<grid, 256, smem>>>(
            bufs[i & 1], bufs[(i + 1) & 1], skip,
            Wd + (size_t)i * 2 * 128 * 256, bd + (size_t)i * 256,
            Wr + (size_t)i * 128 * 128,     br + (size_t)i * 128,
            Ws + (size_t)i * 128 * 512,     bs + (size_t)i * 512,
            Lin, d, (i == 0) ? 1 : 0);
        Lin = Tout;
    }

    post_fused_kernel<<<dim3((FINAL_ + 63) / 64, B_), 256, pf_smem>>>(skip, p1, p2, out);
}

// round 5
// speedup vs baseline: 1.0894x; 1.0894x over previous
#include <cuda_runtime.h>
#include <cuda_bf16.h>
#include <math.h>

#define B_ 8
#define T_ 8192
#define WD_ 128
#define SD_ 512
#define FINAL_ 6145
#define XSTRIDE ((size_t)T_ * WD_)

typedef unsigned long long ull;

// Scratch (static device globals; runtime allocation is forbidden)
__device__ float g_x0[(size_t)B_ * T_ * WD_];          // 32 MB
__device__ float g_x1[(size_t)B_ * T_ * WD_];          // 32 MB
__device__ float g_skip[(size_t)B_ * FINAL_ * SD_];    // ~101 MB

__device__ __forceinline__ float sigm(float x) {
    return 1.0f / (1.0f + __expf(-x));
}

// Packed f32x2 FMA: d = a*b + d (two independent fp32 lanes, one instruction)
__device__ __forceinline__ void fma2(ull& d, ull a, ull b) {
    asm("fma.rn.f32x2 %0, %1, %2, %0;" : "+l"(d) : "l"(a), "l"(b));
}
__device__ __forceinline__ ull dup2(float x) {
    ull r; asm("mov.b64 %0, {%1, %1};" : "=l"(r) : "f"(x)); return r;
}
__device__ __forceinline__ float2 unpack2(ull v) {
    float2 r; asm("mov.b64 {%0, %1}, %2;" : "=f"(r.x), "=f"(r.y) : "l"(v)); return r;
}

// ---------------------------------------------------------------------------
// Embedding: x[b][t][c] = emb[y[b][t]][c], layout [B][T][128] (channel-contig)
// ---------------------------------------------------------------------------
__global__ void embed_kernel(const int* __restrict__ y,
                             const float* __restrict__ emb,
                             float* __restrict__ x) {
    size_t i = (size_t)blockIdx.x * blockDim.x + threadIdx.x;  // float4 index
    size_t bt = i >> 5;
    int c4 = (int)(i & 31);
    int idx = y[bt];
    ((float4*)x)[i] = ((const float4*)(emb + (size_t)idx * WD_))[c4];
}

// ---------------------------------------------------------------------------
// Fused WaveNet layer. Block: 256 threads, 64 time rows.
// Microtile: 8 rows x 8 cols per thread; accumulators packed as f32x2 pairs.
// tn = lane (col group), tm = warp (row group; warp-uniform => A broadcast).
// Acts tile overlays As0 (As0 is dead after conv tap 0).
// ---------------------------------------------------------------------------
#define SMEM_FLOATS (2 * 64 * 128 + 32 * 256)

__global__ __launch_bounds__(256)
void layer_kernel(const float* __restrict__ xin, float* __restrict__ xout,
                  float* __restrict__ skip,
                  const float* __restrict__ Wd,   // [2][128][256]
                  const float* __restrict__ bd,   // [256]
                  const float* __restrict__ Wr,   // [128][128]
                  const float* __restrict__ br,   // [128]
                  const float* __restrict__ Ws,   // [128][512]
                  const float* __restrict__ bs,   // [512]
                  int Lin, int d, int first)
{
    extern __shared__ float sm[];
    float* As0  = sm;                 // [64][128] x[t0+r]  (later reused as Acts)
    float* As1  = sm + 64 * 128;      // [64][128] x[t0+r+d]
    float* Acts = sm;                 // overlay on As0
    float* Bs   = sm + 2 * 64 * 128;  // [32][256] weight slice

    const int Tout = Lin - d;
    const int b   = blockIdx.y;
    const int t0  = blockIdx.x * 64;
    const int tid = threadIdx.x;
    const int tn  = tid & 31;
    const int tm  = tid >> 5;

    const float* xb = xin + (size_t)b * XSTRIDE;

    // Load both A tiles (clamped rows for the ragged tail)
    #pragma unroll
    for (int u = 0; u < 8; u++) {
        int idx = u * 256 + tid;       // float4 index into [64][32]
        int r = idx >> 5, c4 = idx & 31;
        int t = t0 + r; if (t > Tout - 1) t = Tout - 1;
        ((float4*)As0)[idx] = ((const float4*)(xb + (size_t)t * WD_))[c4];
        ((float4*)As1)[idx] = ((const float4*)(xb + (size_t)(t + d) * WD_))[c4];
    }

    // acc pairs: acc[i*4+0]=cols(4tn,4tn+1) acc[i*4+1]=(4tn+2,4tn+3)
    //            acc[i*4+2]=(128+4tn,..+1)  acc[i*4+3]=(128+4tn+2,..+3)
    ull acc[32];
    #pragma unroll
    for (int i = 0; i < 32; i++) acc[i] = 0ULL;

    // ---- Phase 1: conv GEMM (two taps), N=256, K=128 in 4 chunks of 32 ----
    #pragma unroll 1
    for (int h = 0; h < 2; h++) {
        const float* W = Wd + h * (128 * 256);
        const float* A = (h ? As1 : As0) + tm * 8 * 128;
        #pragma unroll 1
        for (int ks = 0; ks < 4; ks++) {
            __syncthreads();
            #pragma unroll
            for (int u = 0; u < 8; u++) {
                int idx = u * 256 + tid;   // 2048 float4 = [32][256]
                ((float4*)Bs)[idx] = ((const float4*)(W + ks * 32 * 256))[idx];
            }
            __syncthreads();
            #pragma unroll
            for (int k4 = 0; k4 < 8; k4++) {
                float4 av[8];
                #pragma unroll
                for (int i = 0; i < 8; i++)
                    av[i] = *(const float4*)&A[i * 128 + ks * 32 + k4 * 4];
                const float* avf = (const float*)av;
                #pragma unroll
                for (int kk = 0; kk < 4; kk++) {
                    int k = k4 * 4 + kk;
                    ulonglong2 b0 = ((const ulonglong2*)(Bs + k * 256))[tn];
                    ulonglong2 b1 = ((const ulonglong2*)(Bs + k * 256 + 128))[tn];
                    #pragma unroll
                    for (int i = 0; i < 8; i++) {
                        ull ad = dup2(avf[i * 4 + kk]);
                        fma2(acc[i*4+0], ad, b0.x);
                        fma2(acc[i*4+1], ad, b0.y);
                        fma2(acc[i*4+2], ad, b1.x);
                        fma2(acc[i*4+3], ad, b1.y);
                    }
                }
            }
        }
    }

    // ---- Gate: acts[c] = tanh(in[c]+bd[c]) * sigmoid(in[c+128]+bd[c+128]) ----
    // (Acts overlays As0; all As0 reads finished in tap h=0, and 4 barriers of
    //  tap h=1 separate them from these writes.)
    {
        float4 bd0 = ((const float4*)bd)[tn];
        float4 bd1 = ((const float4*)(bd + 128))[tn];
        #pragma unroll
        for (int i = 0; i < 8; i++) {
            float2 a0 = unpack2(acc[i*4+0]);
            float2 a1 = unpack2(acc[i*4+1]);
            float2 g0 = unpack2(acc[i*4+2]);
            float2 g1 = unpack2(acc[i*4+3]);
            float4 v;
            v.x = tanhf(a0.x + bd0.x) * sigm(g0.x + bd1.x);
            v.y = tanhf(a0.y + bd0.y) * sigm(g0.y + bd1.y);
            v.z = tanhf(a1.x + bd0.z) * sigm(g1.x + bd1.z);
            v.w = tanhf(a1.y + bd0.w) * sigm(g1.y + bd1.w);
            ((float4*)(Acts + (tm * 8 + i) * 128))[tn] = v;
        }
    }

    const float* ActsA = Acts + tm * 8 * 128;

    // ---- Phase 2: residual GEMM (N=128), K=128 in 4 chunks of 32 ----
    {
        ull racc[16];   // racc[i*2+p] = cols (4tn+2p, 4tn+2p+1)
        #pragma unroll
        for (int i = 0; i < 16; i++) racc[i] = 0ULL;
        #pragma unroll 1
        for (int ks = 0; ks < 4; ks++) {
            __syncthreads();   // first iter also orders gate writes vs Bs reuse
            #pragma unroll
            for (int u = 0; u < 4; u++) {
                int idx = u * 256 + tid;   // 1024 float4 = [32][128]
                ((float4*)Bs)[idx] = ((const float4*)(Wr + ks * 32 * 128))[idx];
            }
            __syncthreads();
            #pragma unroll
            for (int k4 = 0; k4 < 8; k4++) {
                float4 av[8];
                #pragma unroll
                for (int i = 0; i < 8; i++)
                    av[i] = *(const float4*)&ActsA[i * 128 + ks * 32 + k4 * 4];
                const float* avf = (const float*)av;
                #pragma unroll
                for (int kk = 0; kk < 4; kk++) {
                    int k = k4 * 4 + kk;
                    ulonglong2 bv = ((const ulonglong2*)(Bs + k * 128))[tn];
                    #pragma unroll
                    for (int i = 0; i < 8; i++) {
                        ull ad = dup2(avf[i * 4 + kk]);
                        fma2(racc[i*2+0], ad, bv.x);
                        fma2(racc[i*2+1], ad, bv.y);
                    }
                }
            }
        }
        float4 brv = ((const float4*)br)[tn];
        #pragma unroll
        for (int i = 0; i < 8; i++) {
            int t = t0 + tm * 8 + i;
            if (t < Tout) {
                float4 xv = ((const float4*)(As1 + (tm * 8 + i) * 128))[tn];
                float2 r0 = unpack2(racc[i*2+0]);
                float2 r1 = unpack2(racc[i*2+1]);
                float4 o;
                o.x = r0.x + brv.x + xv.x;
                o.y = r0.y + brv.y + xv.y;
                o.z = r1.x + brv.z + xv.z;
                o.w = r1.y + brv.w + xv.w;
                ((float4*)(xout + (size_t)b * XSTRIDE + (size_t)t * WD_))[tn] = o;
            }
        }
    }

    // ---- Phase 3: skip GEMM (N=512, two 256-col chunks), K in 4x32 ----
    const int s0 = Tout - FINAL_;
    #pragma unroll 1
    for (int q = 0; q < 2; q++) {
        #pragma unroll
        for (int i = 0; i < 32; i++) acc[i] = 0ULL;
        #pragma unroll 1
        for (int ks = 0; ks < 4; ks++) {
            __syncthreads();
            #pragma unroll
            for (int u = 0; u < 8; u++) {
                int idx = u * 256 + tid;   // [32][256]
                int row = idx >> 6, c4 = idx & 63;
                ((float4*)Bs)[idx] =
                    ((const float4*)(Ws + (size_t)(ks * 32 + row) * 512 + q * 256))[c4];
            }
            __syncthreads();
            #pragma unroll
            for (int k4 = 0; k4 < 8; k4++) {
                float4 av[8];
                #pragma unroll
                for (int i = 0; i < 8; i++)
                    av[i] = *(const float4*)&ActsA[i * 128 + ks * 32 + k4 * 4];
                const float* avf = (const float*)av;
                #pragma unroll
                for (int kk = 0; kk < 4; kk++) {
                    int k = k4 * 4 + kk;
                    ulonglong2 b0 = ((const ulonglong2*)(Bs + k * 256))[tn];
                    ulonglong2 b1 = ((const ulonglong2*)(Bs + k * 256 + 128))[tn];
                    #pragma unroll
                    for (int i = 0; i < 8; i++) {
                        ull ad = dup2(avf[i * 4 + kk]);
                        fma2(acc[i*4+0], ad, b0.x);
                        fma2(acc[i*4+1], ad, b0.y);
                        fma2(acc[i*4+2], ad, b1.x);
                        fma2(acc[i*4+3], ad, b1.y);
                    }
                }
            }
        }
        float4 bs0 = ((const float4*)(bs + q * 256))[tn];
        float4 bs1 = ((const float4*)(bs + q * 256 + 128))[tn];
        #pragma unroll
        for (int i = 0; i < 8; i++) {
            int t = t0 + tm * 8 + i;
            if (t < Tout && t >= s0) {
                float* p = skip + ((size_t)b * FINAL_ + (t - s0)) * SD_ + q * 256;
                float2 p0 = unpack2(acc[i*4+0]);
                float2 p1 = unpack2(acc[i*4+1]);
                float2 p2 = unpack2(acc[i*4+2]);
                float2 p3 = unpack2(acc[i*4+3]);
                float4 v0, v1;
                v0.x = p0.x + bs0.x; v0.y = p0.y + bs0.y;
                v0.z = p1.x + bs0.z; v0.w = p1.y + bs0.w;
                v1.x = p2.x + bs1.x; v1.y = p2.y + bs1.y;
                v1.z = p3.x + bs1.z; v1.w = p3.y + bs1.w;
                if (!first) {
                    float4 o0 = ((const float4*)p)[tn];
                    float4 o1 = ((const float4*)(p + 128))[tn];
                    v0.x += o0.x; v0.y += o0.y; v0.z += o0.z; v0.w += o0.w;
                    v1.x += o1.x; v1.y += o1.y; v1.z += o1.z; v1.w += o1.w;
                }
                ((float4*)p)[tn] = v0;
                ((float4*)(p + 128))[tn] = v1;
            }
        }
    }
}

// ---------------------------------------------------------------------------
// Fused post stage:
//   hid = relu(relu(skip) @ W1)   (K=512, N=512) -> staged in smem
//   out[b][o][t] = (hid @ W2)[t][o]  (K=512, N=256, transposed store)
// ---------------------------------------------------------------------------
#define PF_SMEM_FLOATS (64 * 512 + 16 * 256 + 64 * 16)

__global__ __launch_bounds__(256)
void post_fused_kernel(const float* __restrict__ skip,
                       const float* __restrict__ W1,
                       const float* __restrict__ W2,
                       float* __restrict__ out)
{
    extern __shared__ float sm2[];
    float* Hid = sm2;                    // [64][512]
    float* Bs  = sm2 + 64 * 512;         // [16][256]
    float* As  = sm2 + 64 * 512 + 16 * 256;  // [64][16]

    const int b  = blockIdx.y;
    const int t0 = blockIdx.x * 64;
    const int tid = threadIdx.x, tn = tid & 31, tm = tid >> 5;

    // ---- Phase A: Hid = relu(relu(skip) @ W1), two 256-col chunks ----
    #pragma unroll 1
    for (int q = 0; q < 2; q++) {
        ull acc[32];
        #pragma unroll
        for (int i = 0; i < 32; i++) acc[i] = 0ULL;

        #pragma unroll 1
        for (int ks = 0; ks < 32; ks++) {
            __syncthreads();
            {
                int r = tid >> 2, c4 = tid & 3;
                int t = t0 + r; if (t > FINAL_ - 1) t = FINAL_ - 1;
                float4 v = ((const float4*)(skip + ((size_t)b * FINAL_ + t) * SD_ + ks * 16))[c4];
                v.x = fmaxf(v.x, 0.0f); v.y = fmaxf(v.y, 0.0f);
                v.z = fmaxf(v.z, 0.0f); v.w = fmaxf(v.w, 0.0f);
                ((float4*)As)[tid] = v;
            }
            #pragma unroll
            for (int u = 0; u < 4; u++) {
                int idx = u * 256 + tid;
                int row = idx >> 6, c4 = idx & 63;
                ((float4*)Bs)[idx] =
                    ((const float4*)(W1 + (size_t)(ks * 16 + row) * 512 + q * 256))[c4];
            }
            __syncthreads();
            #pragma unroll
            for (int k4 = 0; k4 < 4; k4++) {
                float4 av[8];
                #pragma unroll
                for (int i = 0; i < 8; i++)
                    av[i] = *(const float4*)&As[(tm * 8 + i) * 16 + k4 * 4];
                const float* avf = (const float*)av;
                #pragma unroll
                for (int kk = 0; kk < 4; kk++) {
                    int k = k4 * 4 + kk;
                    ulonglong2 b0 = ((const ulonglong2*)(Bs + k * 256))[tn];
                    ulonglong2 b1 = ((const ulonglong2*)(Bs + k * 256 + 128))[tn];
                    #pragma unroll
                    for (int i = 0; i < 8; i++) {
                        ull ad = dup2(avf[i * 4 + kk]);
                        fma2(acc[i*4+0], ad, b0.x);
                        fma2(acc[i*4+1], ad, b0.y);
                        fma2(acc[i*4+2], ad, b1.x);
                        fma2(acc[i*4+3], ad, b1.y);
                    }
                }
            }
        }
        // Store relu(acc) into the Hid smem tile
        #pragma unroll
        for (int i = 0; i < 8; i++) {
            float* p = Hid + (tm * 8 + i) * 512 + q * 256;
            float2 p0 = unpack2(acc[i*4+0]);
            float2 p1 = unpack2(acc[i*4+1]);
            float2 p2 = unpack2(acc[i*4+2]);
            float2 p3 = unpack2(acc[i*4+3]);
            float4 v0, v1;
            v0.x = fmaxf(p0.x, 0.0f); v0.y = fmaxf(p0.y, 0.0f);
            v0.z = fmaxf(p1.x, 0.0f); v0.w = fmaxf(p1.y, 0.0f);
            v1.x = fmaxf(p2.x, 0.0f); v1.y = fmaxf(p2.y, 0.0f);
            v1.z = fmaxf(p3.x, 0.0f); v1.w = fmaxf(p3.y, 0.0f);
            ((float4*)p)[tn] = v0;
            ((float4*)(p + 128))[tn] = v1;
        }
    }

    // ---- Phase B: out = Hid @ W2 (K=512, N=256), transposed store ----
    {
        ull acc[32];
        #pragma unroll
        for (int i = 0; i < 32; i++) acc[i] = 0ULL;

        const float* HidA = Hid + tm * 8 * 512;
        #pragma unroll 1
        for (int ks = 0; ks < 32; ks++) {
            __syncthreads();   // first iter also orders Hid writes vs reads
            #pragma unroll
            for (int u = 0; u < 4; u++) {
                int idx = u * 256 + tid;
                int row = idx >> 6, c4 = idx & 63;
                ((float4*)Bs)[idx] =
                    ((const float4*)(W2 + (size_t)(ks * 16 + row) * 256))[c4];
            }
            __syncthreads();
            #pragma unroll
            for (int k4 = 0; k4 < 4; k4++) {
                float4 av[8];
                #pragma unroll
                for (int i = 0; i < 8; i++)
                    av[i] = *(const float4*)&HidA[i * 512 + ks * 16 + k4 * 4];
                const float* avf = (const float*)av;
                #pragma unroll
                for (int kk = 0; kk < 4; kk++) {
                    int k = k4 * 4 + kk;
                    ulonglong2 b0 = ((const ulonglong2*)(Bs + k * 256))[tn];
                    ulonglong2 b1 = ((const ulonglong2*)(Bs + k * 256 + 128))[tn];
                    #pragma unroll
                    for (int i = 0; i < 8; i++) {
                        ull ad = dup2(avf[i * 4 + kk]);
                        fma2(acc[i*4+0], ad, b0.x);
                        fma2(acc[i*4+1], ad, b0.y);
                        fma2(acc[i*4+2], ad, b1.x);
                        fma2(acc[i*4+3], ad, b1.y);
                    }
                }
            }
        }
        #pragma unroll
        for (int i = 0; i < 8; i++) {
            int t = t0 + tm * 8 + i;
            if (t < FINAL_) {
                float2 p0 = unpack2(acc[i*4+0]);
                float2 p1 = unpack2(acc[i*4+1]);
                float2 p2 = unpack2(acc[i*4+2]);
                float2 p3 = unpack2(acc[i*4+3]);
                float vv[8] = {p0.x, p0.y, p1.x, p1.y, p2.x, p2.y, p3.x, p3.y};
                #pragma unroll
                for (int j = 0; j < 4; j++) {
                    out[((size_t)b * 256 + (tn * 4 + j)) * FINAL_ + t]       = vv[j];
                    out[((size_t)b * 256 + (128 + tn * 4 + j)) * FINAL_ + t] = vv[4 + j];
                }
            }
        }
    }
}

// ---------------------------------------------------------------------------
extern "C" void kernel_launch(void* const* d_in, const int* in_sizes, int n_in,
                              void* d_out, int out_size)
{
    const int*   y   = (const int*)  d_in[0];
    const float* emb = (const float*)d_in[1];
    const float* Wd  = (const float*)d_in[2];
    const float* bd  = (const float*)d_in[3];
    const float* Wr  = (const float*)d_in[4];
    const float* br  = (const float*)d_in[5];
    const float* Ws  = (const float*)d_in[6];
    const float* bs  = (const float*)d_in[7];
    const float* p1  = (const float*)d_in[8];
    const float* p2  = (const float*)d_in[9];
    float* out = (float*)d_out;

    float *x0, *x1, *skip;
    cudaGetSymbolAddress((void**)&x0,   g_x0);
    cudaGetSymbolAddress((void**)&x1,   g_x1);
    cudaGetSymbolAddress((void**)&skip, g_skip);

    static const int dil[20] = {1,2,4,8,16,32,64,128,256,512,
                                1,2,4,8,16,32,64,128,256,512};

    size_t smem = SMEM_FLOATS * sizeof(float);
    cudaFuncSetAttribute(layer_kernel,
                         cudaFuncAttributeMaxDynamicSharedMemorySize, (int)smem);
    size_t pf_smem = PF_SMEM_FLOATS * sizeof(float);
    cudaFuncSetAttribute(post_fused_kernel,
                         cudaFuncAttributeMaxDynamicSharedMemorySize, (int)pf_smem);

    embed_kernel<<<(B_ * T_ * WD_ / 4) / 256, 256>>>(y, emb, x0);

    float* bufs[2] = {x0, x1};
    int Lin = T_;
    for (int i = 0; i < 20; i++) {
        int d = dil[i];
        int Tout = Lin - d;
        dim3 grid((Tout + 63) / 64, B_);
        layer_kernel<<<grid, 256, smem>>>(
            bufs[i & 1], bufs[(i + 1) & 1], skip,
            Wd + (size_t)i * 2 * 128 * 256, bd + (size_t)i * 256,
            Wr + (size_t)i * 128 * 128,     br + (size_t)i * 128,
            Ws + (size_t)i * 128 * 512,     bs + (size_t)i * 512,
            Lin, d, (i == 0) ? 1 : 0);
        Lin = Tout;
    }

    post_fused_kernel<<<dim3((FINAL_ + 63) / 64, B_), 256, pf_smem>>>(skip, p1, p2, out);
}

// round 6
// speedup vs baseline: 1.0938x; 1.0041x over previous
#include <cuda_runtime.h>
#include <cuda_bf16.h>
#include <math.h>

#define B_ 8
#define T_ 8192
#define WD_ 128
#define SD_ 512
#define FINAL_ 6145
#define XSTRIDE ((size_t)T_ * WD_)

typedef unsigned long long ull;

// Scratch (static device globals; runtime allocation is forbidden)
__device__ float g_x0[(size_t)B_ * T_ * WD_];          // 32 MB
__device__ float g_x1[(size_t)B_ * T_ * WD_];          // 32 MB
__device__ float g_skip[(size_t)B_ * FINAL_ * SD_];    // ~101 MB

__device__ __forceinline__ float sigm(float x) {
    return 1.0f / (1.0f + __expf(-x));
}

// Packed f32x2 FMA: d = a*b + d (two independent fp32 lanes, one instruction)
__device__ __forceinline__ void fma2(ull& d, ull a, ull b) {
    asm("fma.rn.f32x2 %0, %1, %2, %0;" : "+l"(d) : "l"(a), "l"(b));
}
__device__ __forceinline__ ull dup2(float x) {
    ull r; asm("mov.b64 %0, {%1, %1};" : "=l"(r) : "f"(x)); return r;
}
__device__ __forceinline__ float2 unpack2(ull v) {
    float2 r; asm("mov.b64 {%0, %1}, %2;" : "=f"(r.x), "=f"(r.y) : "l"(v)); return r;
}

// ---------------------------------------------------------------------------
// Embedding: x[b][t][c] = emb[y[b][t]][c], layout [B][T][128] (channel-contig)
// ---------------------------------------------------------------------------
__global__ void embed_kernel(const int* __restrict__ y,
                             const float* __restrict__ emb,
                             float* __restrict__ x) {
    size_t i = (size_t)blockIdx.x * blockDim.x + threadIdx.x;  // float4 index
    size_t bt = i >> 5;
    int c4 = (int)(i & 31);
    int idx = y[bt];
    ((float4*)x)[i] = ((const float4*)(emb + (size_t)idx * WD_))[c4];
}

// ---------------------------------------------------------------------------
// Fused WaveNet layer. Block: 256 threads, 64 time rows.
// Microtile: 8 rows x 8 cols per thread; accumulators packed as f32x2 pairs.
// tn = lane (col group), tm = warp (row group; warp-uniform => A broadcast).
// Acts tile overlays As0 (As0 is dead after conv tap 0).
// ---------------------------------------------------------------------------
#define SMEM_FLOATS (2 * 64 * 128 + 32 * 256)

__global__ __launch_bounds__(256)
void layer_kernel(const float* __restrict__ xin, float* __restrict__ xout,
                  float* __restrict__ skip,
                  const float* __restrict__ Wd,   // [2][128][256]
                  const float* __restrict__ bd,   // [256]
                  const float* __restrict__ Wr,   // [128][128]
                  const float* __restrict__ br,   // [128]
                  const float* __restrict__ Ws,   // [128][512]
                  const float* __restrict__ bs,   // [512]
                  int Lin, int d, int first)
{
    extern __shared__ float sm[];
    float* As0  = sm;                 // [64][128] x[t0+r]  (later reused as Acts)
    float* As1  = sm + 64 * 128;      // [64][128] x[t0+r+d]
    float* Acts = sm;                 // overlay on As0
    float* Bs   = sm + 2 * 64 * 128;  // [32][256] weight slice

    const int Tout = Lin - d;
    const int b   = blockIdx.y;
    const int t0  = blockIdx.x * 64;
    const int tid = threadIdx.x;
    const int tn  = tid & 31;
    const int tm  = tid >> 5;

    const float* xb = xin + (size_t)b * XSTRIDE;

    // Load both A tiles (clamped rows for the ragged tail)
    #pragma unroll
    for (int u = 0; u < 8; u++) {
        int idx = u * 256 + tid;       // float4 index into [64][32]
        int r = idx >> 5, c4 = idx & 31;
        int t = t0 + r; if (t > Tout - 1) t = Tout - 1;
        ((float4*)As0)[idx] = ((const float4*)(xb + (size_t)t * WD_))[c4];
        ((float4*)As1)[idx] = ((const float4*)(xb + (size_t)(t + d) * WD_))[c4];
    }

    // acc pairs: acc[i*4+0]=cols(4tn,4tn+1) acc[i*4+1]=(4tn+2,4tn+3)
    //            acc[i*4+2]=(128+4tn,..+1)  acc[i*4+3]=(128+4tn+2,..+3)
    ull acc[32];
    #pragma unroll
    for (int i = 0; i < 32; i++) acc[i] = 0ULL;

    // ---- Phase 1: conv GEMM (two taps), N=256, K=128 in 4 chunks of 32 ----
    #pragma unroll 1
    for (int h = 0; h < 2; h++) {
        const float* W = Wd + h * (128 * 256);
        const float* A = (h ? As1 : As0) + tm * 8 * 128;
        #pragma unroll 1
        for (int ks = 0; ks < 4; ks++) {
            __syncthreads();
            #pragma unroll
            for (int u = 0; u < 8; u++) {
                int idx = u * 256 + tid;   // 2048 float4 = [32][256]
                ((float4*)Bs)[idx] = ((const float4*)(W + ks * 32 * 256))[idx];
            }
            __syncthreads();
            #pragma unroll
            for (int k4 = 0; k4 < 8; k4++) {
                float4 av[8];
                #pragma unroll
                for (int i = 0; i < 8; i++)
                    av[i] = *(const float4*)&A[i * 128 + ks * 32 + k4 * 4];
                const float* avf = (const float*)av;
                #pragma unroll
                for (int kk = 0; kk < 4; kk++) {
                    int k = k4 * 4 + kk;
                    ulonglong2 b0 = ((const ulonglong2*)(Bs + k * 256))[tn];
                    ulonglong2 b1 = ((const ulonglong2*)(Bs + k * 256 + 128))[tn];
                    #pragma unroll
                    for (int i = 0; i < 8; i++) {
                        ull ad = dup2(avf[i * 4 + kk]);
                        fma2(acc[i*4+0], ad, b0.x);
                        fma2(acc[i*4+1], ad, b0.y);
                        fma2(acc[i*4+2], ad, b1.x);
                        fma2(acc[i*4+3], ad, b1.y);
                    }
                }
            }
        }
    }

    // ---- Gate: acts[c] = tanh(in[c]+bd[c]) * sigmoid(in[c+128]+bd[c+128]) ----
    // (Acts overlays As0; all As0 reads finished in tap h=0, and 4 barriers of
    //  tap h=1 separate them from these writes.)
    {
        float4 bd0 = ((const float4*)bd)[tn];
        float4 bd1 = ((const float4*)(bd + 128))[tn];
        #pragma unroll
        for (int i = 0; i < 8; i++) {
            float2 a0 = unpack2(acc[i*4+0]);
            float2 a1 = unpack2(acc[i*4+1]);
            float2 g0 = unpack2(acc[i*4+2]);
            float2 g1 = unpack2(acc[i*4+3]);
            float4 v;
            v.x = tanhf(a0.x + bd0.x) * sigm(g0.x + bd1.x);
            v.y = tanhf(a0.y + bd0.y) * sigm(g0.y + bd1.y);
            v.z = tanhf(a1.x + bd0.z) * sigm(g1.x + bd1.z);
            v.w = tanhf(a1.y + bd0.w) * sigm(g1.y + bd1.w);
            ((float4*)(Acts + (tm * 8 + i) * 128))[tn] = v;
        }
    }

    const float* ActsA = Acts + tm * 8 * 128;

    // ---- Phase 2: residual GEMM (N=128), K=128 in 4 chunks of 32 ----
    {
        ull racc[16];   // racc[i*2+p] = cols (4tn+2p, 4tn+2p+1)
        #pragma unroll
        for (int i = 0; i < 16; i++) racc[i] = 0ULL;
        #pragma unroll 1
        for (int ks = 0; ks < 4; ks++) {
            __syncthreads();   // first iter also orders gate writes vs Bs reuse
            #pragma unroll
            for (int u = 0; u < 4; u++) {
                int idx = u * 256 + tid;   // 1024 float4 = [32][128]
                ((float4*)Bs)[idx] = ((const float4*)(Wr + ks * 32 * 128))[idx];
            }
            __syncthreads();
            #pragma unroll
            for (int k4 = 0; k4 < 8; k4++) {
                float4 av[8];
                #pragma unroll
                for (int i = 0; i < 8; i++)
                    av[i] = *(const float4*)&ActsA[i * 128 + ks * 32 + k4 * 4];
                const float* avf = (const float*)av;
                #pragma unroll
                for (int kk = 0; kk < 4; kk++) {
                    int k = k4 * 4 + kk;
                    ulonglong2 bv = ((const ulonglong2*)(Bs + k * 128))[tn];
                    #pragma unroll
                    for (int i = 0; i < 8; i++) {
                        ull ad = dup2(avf[i * 4 + kk]);
                        fma2(racc[i*2+0], ad, bv.x);
                        fma2(racc[i*2+1], ad, bv.y);
                    }
                }
            }
        }
        float4 brv = ((const float4*)br)[tn];
        #pragma unroll
        for (int i = 0; i < 8; i++) {
            int t = t0 + tm * 8 + i;
            if (t < Tout) {
                float4 xv = ((const float4*)(As1 + (tm * 8 + i) * 128))[tn];
                float2 r0 = unpack2(racc[i*2+0]);
                float2 r1 = unpack2(racc[i*2+1]);
                float4 o;
                o.x = r0.x + brv.x + xv.x;
                o.y = r0.y + brv.y + xv.y;
                o.z = r1.x + brv.z + xv.z;
                o.w = r1.y + brv.w + xv.w;
                ((float4*)(xout + (size_t)b * XSTRIDE + (size_t)t * WD_))[tn] = o;
            }
        }
    }

    // ---- Phase 3: skip GEMM (N=512, two 256-col chunks), K in 4x32 ----
    const int s0 = Tout - FINAL_;
    #pragma unroll 1
    for (int q = 0; q < 2; q++) {
        #pragma unroll
        for (int i = 0; i < 32; i++) acc[i] = 0ULL;
        #pragma unroll 1
        for (int ks = 0; ks < 4; ks++) {
            __syncthreads();
            #pragma unroll
            for (int u = 0; u < 8; u++) {
                int idx = u * 256 + tid;   // [32][256]
                int row = idx >> 6, c4 = idx & 63;
                ((float4*)Bs)[idx] =
                    ((const float4*)(Ws + (size_t)(ks * 32 + row) * 512 + q * 256))[c4];
            }
            __syncthreads();
            #pragma unroll
            for (int k4 = 0; k4 < 8; k4++) {
                float4 av[8];
                #pragma unroll
                for (int i = 0; i < 8; i++)
                    av[i] = *(const float4*)&ActsA[i * 128 + ks * 32 + k4 * 4];
                const float* avf = (const float*)av;
                #pragma unroll
                for (int kk = 0; kk < 4; kk++) {
                    int k = k4 * 4 + kk;
                    ulonglong2 b0 = ((const ulonglong2*)(Bs + k * 256))[tn];
                    ulonglong2 b1 = ((const ulonglong2*)(Bs + k * 256 + 128))[tn];
                    #pragma unroll
                    for (int i = 0; i < 8; i++) {
                        ull ad = dup2(avf[i * 4 + kk]);
                        fma2(acc[i*4+0], ad, b0.x);
                        fma2(acc[i*4+1], ad, b0.y);
                        fma2(acc[i*4+2], ad, b1.x);
                        fma2(acc[i*4+3], ad, b1.y);
                    }
                }
            }
        }
        float4 bs0 = ((const float4*)(bs + q * 256))[tn];
        float4 bs1 = ((const float4*)(bs + q * 256 + 128))[tn];
        #pragma unroll
        for (int i = 0; i < 8; i++) {
            int t = t0 + tm * 8 + i;
            if (t < Tout && t >= s0) {
                float* p = skip + ((size_t)b * FINAL_ + (t - s0)) * SD_ + q * 256;
                float2 p0 = unpack2(acc[i*4+0]);
                float2 p1 = unpack2(acc[i*4+1]);
                float2 p2 = unpack2(acc[i*4+2]);
                float2 p3 = unpack2(acc[i*4+3]);
                float4 v0, v1;
                v0.x = p0.x + bs0.x; v0.y = p0.y + bs0.y;
                v0.z = p1.x + bs0.z; v0.w = p1.y + bs0.w;
                v1.x = p2.x + bs1.x; v1.y = p2.y + bs1.y;
                v1.z = p3.x + bs1.z; v1.w = p3.y + bs1.w;
                if (!first) {
                    float4 o0 = ((const float4*)p)[tn];
                    float4 o1 = ((const float4*)(p + 128))[tn];
                    v0.x += o0.x; v0.y += o0.y; v0.z += o0.z; v0.w += o0.w;
                    v1.x += o1.x; v1.y += o1.y; v1.z += o1.z; v1.w += o1.w;
                }
                ((float4*)p)[tn] = v0;
                ((float4*)(p + 128))[tn] = v1;
            }
        }
    }
}

// ---------------------------------------------------------------------------
// Fused post stage:
//   hid = relu(relu(skip) @ W1)   (K=512, N=512) -> staged in smem
//   out[b][o][t] = (hid @ W2)[t][o]  (K=512, N=256, transposed store)
// ---------------------------------------------------------------------------
#define PF_SMEM_FLOATS (64 * 512 + 16 * 256 + 64 * 16)

__global__ __launch_bounds__(256)
void post_fused_kernel(const float* __restrict__ skip,
                       const float* __restrict__ W1,
                       const float* __restrict__ W2,
                       float* __restrict__ out)
{
    extern __shared__ float sm2[];
    float* Hid = sm2;                    // [64][512]
    float* Bs  = sm2 + 64 * 512;         // [16][256]
    float* As  = sm2 + 64 * 512 + 16 * 256;  // [64][16]

    const int b  = blockIdx.y;
    const int t0 = blockIdx.x * 64;
    const int tid = threadIdx.x, tn = tid & 31, tm = tid >> 5;

    // ---- Phase A: Hid = relu(relu(skip) @ W1), two 256-col chunks ----
    #pragma unroll 1
    for (int q = 0; q < 2; q++) {
        ull acc[32];
        #pragma unroll
        for (int i = 0; i < 32; i++) acc[i] = 0ULL;

        #pragma unroll 1
        for (int ks = 0; ks < 32; ks++) {
            __syncthreads();
            {
                int r = tid >> 2, c4 = tid & 3;
                int t = t0 + r; if (t > FINAL_ - 1) t = FINAL_ - 1;
                float4 v = ((const float4*)(skip + ((size_t)b * FINAL_ + t) * SD_ + ks * 16))[c4];
                v.x = fmaxf(v.x, 0.0f); v.y = fmaxf(v.y, 0.0f);
                v.z = fmaxf(v.z, 0.0f); v.w = fmaxf(v.w, 0.0f);
                ((float4*)As)[tid] = v;
            }
            #pragma unroll
            for (int u = 0; u < 4; u++) {
                int idx = u * 256 + tid;
                int row = idx >> 6, c4 = idx & 63;
                ((float4*)Bs)[idx] =
                    ((const float4*)(W1 + (size_t)(ks * 16 + row) * 512 + q * 256))[c4];
            }
            __syncthreads();
            #pragma unroll
            for (int k4 = 0; k4 < 4; k4++) {
                float4 av[8];
                #pragma unroll
                for (int i = 0; i < 8; i++)
                    av[i] = *(const float4*)&As[(tm * 8 + i) * 16 + k4 * 4];
                const float* avf = (const float*)av;
                #pragma unroll
                for (int kk = 0; kk < 4; kk++) {
                    int k = k4 * 4 + kk;
                    ulonglong2 b0 = ((const ulonglong2*)(Bs + k * 256))[tn];
                    ulonglong2 b1 = ((const ulonglong2*)(Bs + k * 256 + 128))[tn];
                    #pragma unroll
                    for (int i = 0; i < 8; i++) {
                        ull ad = dup2(avf[i * 4 + kk]);
                        fma2(acc[i*4+0], ad, b0.x);
                        fma2(acc[i*4+1], ad, b0.y);
                        fma2(acc[i*4+2], ad, b1.x);
                        fma2(acc[i*4+3], ad, b1.y);
                    }
                }
            }
        }
        // Store relu(acc) into the Hid smem tile
        #pragma unroll
        for (int i = 0; i < 8; i++) {
            float* p = Hid + (tm * 8 + i) * 512 + q * 256;
            float2 p0 = unpack2(acc[i*4+0]);
            float2 p1 = unpack2(acc[i*4+1]);
            float2 p2 = unpack2(acc[i*4+2]);
            float2 p3 = unpack2(acc[i*4+3]);
            float4 v0, v1;
            v0.x = fmaxf(p0.x, 0.0f); v0.y = fmaxf(p0.y, 0.0f);
            v0.z = fmaxf(p1.x, 0.0f); v0.w = fmaxf(p1.y, 0.0f);
            v1.x = fmaxf(p2.x, 0.0f); v1.y = fmaxf(p2.y, 0.0f);
            v1.z = fmaxf(p3.x, 0.0f); v1.w = fmaxf(p3.y, 0.0f);
            ((float4*)p)[tn] = v0;
            ((float4*)(p + 128))[tn] = v1;
        }
    }

    // ---- Phase B: out = Hid @ W2 (K=512, N=256), transposed store ----
    {
        ull acc[32];
        #pragma unroll
        for (int i = 0; i < 32; i++) acc[i] = 0ULL;

        const float* HidA = Hid + tm * 8 * 512;
        #pragma unroll 1
        for (int ks = 0; ks < 32; ks++) {
            __syncthreads();   // first iter also orders Hid writes vs reads
            #pragma unroll
            for (int u = 0; u < 4; u++) {
                int idx = u * 256 + tid;
                int row = idx >> 6, c4 = idx & 63;
                ((float4*)Bs)[idx] =
                    ((const float4*)(W2 + (size_t)(ks * 16 + row) * 256))[c4];
            }
            __syncthreads();
            #pragma unroll
            for (int k4 = 0; k4 < 4; k4++) {
                float4 av[8];
                #pragma unroll
                for (int i = 0; i < 8; i++)
                    av[i] = *(const float4*)&HidA[i * 512 + ks * 16 + k4 * 4];
                const float* avf = (const float*)av;
                #pragma unroll
                for (int kk = 0; kk < 4; kk++) {
                    int k = k4 * 4 + kk;
                    ulonglong2 b0 = ((const ulonglong2*)(Bs + k * 256))[tn];
                    ulonglong2 b1 = ((const ulonglong2*)(Bs + k * 256 + 128))[tn];
                    #pragma unroll
                    for (int i = 0; i < 8; i++) {
                        ull ad = dup2(avf[i * 4 + kk]);
                        fma2(acc[i*4+0], ad, b0.x);
                        fma2(acc[i*4+1], ad, b0.y);
                        fma2(acc[i*4+2], ad, b1.x);
                        fma2(acc[i*4+3], ad, b1.y);
                    }
                }
            }
        }
        #pragma unroll
        for (int i = 0; i < 8; i++) {
            int t = t0 + tm * 8 + i;
            if (t < FINAL_) {
                float2 p0 = unpack2(acc[i*4+0]);
                float2 p1 = unpack2(acc[i*4+1]);
                float2 p2 = unpack2(acc[i*4+2]);
                float2 p3 = unpack2(acc[i*4+3]);
                float vv[8] = {p0.x, p0.y, p1.x, p1.y, p2.x, p2.y, p3.x, p3.y};
                #pragma unroll
                for (int j = 0; j < 4; j++) {
                    out[((size_t)b * 256 + (tn * 4 + j)) * FINAL_ + t]       = vv[j];
                    out[((size_t)b * 256 + (128 + tn * 4 + j)) * FINAL_ + t] = vv[4 + j];
                }
            }
        }
    }
}

// ---------------------------------------------------------------------------
extern "C" void kernel_launch(void* const* d_in, const int* in_sizes, int n_in,
                              void* d_out, int out_size)
{
    const int*   y   = (const int*)  d_in[0];
    const float* emb = (const float*)d_in[1];
    const float* Wd  = (const float*)d_in[2];
    const float* bd  = (const float*)d_in[3];
    const float* Wr  = (const float*)d_in[4];
    const float* br  = (const float*)d_in[5];
    const float* Ws  = (const float*)d_in[6];
    const float* bs  = (const float*)d_in[7];
    const float* p1  = (const float*)d_in[8];
    const float* p2  = (const float*)d_in[9];
    float* out = (float*)d_out;

    float *x0, *x1, *skip;
    cudaGetSymbolAddress((void**)&x0,   g_x0);
    cudaGetSymbolAddress((void**)&x1,   g_x1);
    cudaGetSymbolAddress((void**)&skip, g_skip);

    static const int dil[20] = {1,2,4,8,16,32,64,128,256,512,
                                1,2,4,8,16,32,64,128,256,512};

    size_t smem = SMEM_FLOATS * sizeof(float);
    cudaFuncSetAttribute(layer_kernel,
                         cudaFuncAttributeMaxDynamicSharedMemorySize, (int)smem);
    size_t pf_smem = PF_SMEM_FLOATS * sizeof(float);
    cudaFuncSetAttribute(post_fused_kernel,
                         cudaFuncAttributeMaxDynamicSharedMemorySize, (int)pf_smem);

    embed_kernel<<<(B_ * T_ * WD_ / 4) / 256, 256>>>(y, emb, x0);

    float* bufs[2] = {x0, x1};
    int Lin = T_;
    for (int i = 0; i < 20; i++) {
        int d = dil[i];
        int Tout = Lin - d;
        dim3 grid((Tout + 63) / 64, B_);
        layer_kernel<<<grid, 256, smem>>>(
            bufs[i & 1], bufs[(i + 1) & 1], skip,
            Wd + (size_t)i * 2 * 128 * 256, bd + (size_t)i * 256,
            Wr + (size_t)i * 128 * 128,     br + (size_t)i * 128,
            Ws + (size_t)i * 128 * 512,     bs + (size_t)i * 512,
            Lin, d, (i == 0) ? 1 : 0);
        Lin = Tout;
    }

    post_fused_kernel<<<dim3((FINAL_ + 63) / 64, B_), 256, pf_smem>>>(skip, p1, p2, out);
}